// round 13
// baseline (speedup 1.0000x reference)
#include <cuda_runtime.h>
#include <cuda_fp16.h>
#include <mma.h>
#include <math.h>
#include <cstdint>

using namespace nvcuda;

#define N_NODES 100000
#define N_EDGES 1000000
#define KD 128
#define VD 64
#define AGGD 192   // KD + VD
#define NBLK 391   // ceil(N_NODES / 256)

// ---------------- scratch (static device allocations, graph-safe) ----------
__device__ __align__(16) int4   g_csr[N_EDGES];      // CSR-ordered {h,a,v,score}
__device__ __align__(16) __half g_attH[N_NODES * KD];
__device__ __align__(16) __half g_valH[N_NODES * VD];
__device__ __align__(16) __half g_aggH[N_NODES * AGGD];  // fp16 aggregated rows
__device__ __align__(16) __half g_Wt[KD * AGGD];         // Wt[n][k] = W[k][n]
__device__ float g_rowsum[N_NODES];
__device__ float g_sent[N_NODES];
__device__ float g_satt[N_NODES];
__device__ int   g_deg[N_NODES];
__device__ int   g_off[N_NODES];
__device__ int   g_cursor[N_NODES];
__device__ int   g_bsum[NBLK];
__device__ int   g_boff[NBLK];
__device__ int   g_idx64;

// ---------------- dtype sniff: int64 vs int32 triples (parallel) -----------
__global__ void sniff_kernel(const int* tri32) {
    int t = threadIdx.x;
    int bad = (tri32[2 * t + 1] != 0) ? 1 : 0;
    int any = __syncthreads_or(bad);
    if (t == 0) g_idx64 = any ? 0 : 1;
}

// ------- val fp16 conversion + per-node counter resets ----------------------
__global__ void valconv_kernel(const float* __restrict__ valf) {
    int i = blockIdx.x * blockDim.x + threadIdx.x;
    if (i < N_NODES) {
        g_deg[i] = 0;
        g_rowsum[i] = 0.f;
    }
    int n4 = N_NODES * VD / 4;
    if (i >= n4) return;
    float4 v = reinterpret_cast<const float4*>(valf)[i];
    __half2 h0 = __floats2half2_rn(v.x, v.y);
    __half2 h1 = __floats2half2_rn(v.z, v.w);
    uint2 packed;
    packed.x = *reinterpret_cast<unsigned*>(&h0);
    packed.y = *reinterpret_cast<unsigned*>(&h1);
    *reinterpret_cast<uint2*>(g_valH + i * 4) = packed;
}

// ---------------- prepack W^T as fp16: Wt[n][k] = W[k][n] -------------------
__global__ void prepack_kernel(const float* __restrict__ W) {
    int idx = blockIdx.x * blockDim.x + threadIdx.x;
    if (idx >= KD * AGGD) return;
    int n = idx / AGGD;        // 0..127
    int k = idx % AGGD;        // 0..191
    g_Wt[idx] = __float2half_rn(W[k * KD + n]);
}

// ---------------- degree histogram (h column only) ---------------------------
__global__ void deg_kernel(const int* __restrict__ tri32) {
    int e = blockIdx.x * blockDim.x + threadIdx.x;
    if (e >= N_EDGES) return;
    int h = g_idx64 ? tri32[6 * e] : tri32[3 * e];
    atomicAdd(&g_deg[h], 1);
}

// ------- per-node score pre-reduction + att fp16 conversion ----------------
__global__ void score_pre_kernel(const float* __restrict__ ent,
                                 const float* __restrict__ att,
                                 const float* __restrict__ aw) {
    int warp = (blockIdx.x * blockDim.x + threadIdx.x) >> 5;
    int lane = threadIdx.x & 31;
    if (warp >= N_NODES) return;

    const float4* ent4 = reinterpret_cast<const float4*>(ent);
    const float4* att4 = reinterpret_cast<const float4*>(att);
    const float4* aw4  = reinterpret_cast<const float4*>(aw);

    float4 e = ent4[warp * 32 + lane];
    float4 a = att4[warp * 32 + lane];
    float4 we = __ldg(&aw4[lane]);
    float4 wa = __ldg(&aw4[32 + lane]);

    __half2 h0 = __floats2half2_rn(a.x, a.y);
    __half2 h1 = __floats2half2_rn(a.z, a.w);
    uint2 packed;
    packed.x = *reinterpret_cast<unsigned*>(&h0);
    packed.y = *reinterpret_cast<unsigned*>(&h1);
    *reinterpret_cast<uint2*>(g_attH + warp * KD + lane * 4) = packed;

    float se = e.x * we.x + e.y * we.y + e.z * we.z + e.w * we.w;
    float sa = a.x * wa.x + a.y * wa.y + a.z * wa.z + a.w * wa.w;
    #pragma unroll
    for (int o = 16; o; o >>= 1) {
        se += __shfl_xor_sync(0xFFFFFFFFu, se, o);
        sa += __shfl_xor_sync(0xFFFFFFFFu, sa, o);
    }
    if (lane == 0) {
        g_sent[warp] = se;
        g_satt[warp] = sa;
    }
}

// ---------------- 3-phase exclusive scan over degrees -----------------------
__global__ void scan_a_kernel() {
    __shared__ int sh[256];
    int t = threadIdx.x, b = blockIdx.x;
    int node = b * 256 + t;
    sh[t] = (node < N_NODES) ? g_deg[node] : 0;
    __syncthreads();
    #pragma unroll
    for (int d = 128; d; d >>= 1) {
        if (t < d) sh[t] += sh[t + d];
        __syncthreads();
    }
    if (t == 0) g_bsum[b] = sh[0];
}

__global__ void scan_b_kernel() {
    __shared__ int sh[512];
    int t = threadIdx.x;
    int v = (t < NBLK) ? g_bsum[t] : 0;
    sh[t] = v;
    __syncthreads();
    #pragma unroll
    for (int d = 1; d < 512; d <<= 1) {
        int x = (t >= d) ? sh[t - d] : 0;
        __syncthreads();
        sh[t] += x;
        __syncthreads();
    }
    if (t < NBLK) g_boff[t] = sh[t] - v;   // exclusive
}

__global__ void scan_c_kernel() {
    __shared__ int sh[256];
    int t = threadIdx.x, b = blockIdx.x;
    int node = b * 256 + t;
    int v = (node < N_NODES) ? g_deg[node] : 0;
    sh[t] = v;
    __syncthreads();
    #pragma unroll
    for (int d = 1; d < 256; d <<= 1) {
        int x = (t >= d) ? sh[t - d] : 0;
        __syncthreads();
        sh[t] += x;
        __syncthreads();
    }
    if (node < N_NODES) {
        int off = g_boff[b] + sh[t] - v;
        g_off[node] = off;
        g_cursor[node] = off;
    }
}

// ------- fused score + CSR fill: compute score, write record in place -------
__global__ void score_fill_kernel(const void* __restrict__ tri,
                                  const float* __restrict__ ab) {
    int e = blockIdx.x * blockDim.x + threadIdx.x;
    if (e >= N_EDGES) return;
    int h, a, v;
    if (g_idx64) {
        const long long* t = reinterpret_cast<const long long*>(tri) + 3LL * e;
        h = (int)t[0]; a = (int)t[1]; v = (int)t[2];
    } else {
        const int* t = reinterpret_cast<const int*>(tri) + 3 * e;
        h = t[0]; a = t[1]; v = t[2];
    }
    float s = g_sent[h] + g_satt[a] + __ldg(&ab[0]);
    s = s > 0.f ? s : 0.2f * s;                 // leaky_relu(0.2)
    float sc = __expf(s);
    atomicAdd(&g_rowsum[h], sc);
    int pos = atomicAdd(&g_cursor[h], 1);
    g_csr[pos] = make_int4(h, a, v, __float_as_int(sc));
}

// ------- gather-side weighted aggregation -> fp16 rows -----------------------
// Predicated 8-wide batches: ALL gathers issue at MLP 16; invalid slots clamp
// to edge 0 of the window (uniform shfl src, same-line L1 hit) and carry s=0.
__device__ __forceinline__ void acc_edge(uint2 ua, uint2 uv, float s, int lane,
                                         float4& accA, float4& accV) {
    __half2 h0 = *reinterpret_cast<__half2*>(&ua.x);
    __half2 h1 = *reinterpret_cast<__half2*>(&ua.y);
    float2 f0 = __half22float2(h0);
    float2 f1 = __half22float2(h1);
    accA.x += f0.x * s; accA.y += f0.y * s;
    accA.z += f1.x * s; accA.w += f1.y * s;
    if (lane < 16) {
        __half2 g0 = *reinterpret_cast<__half2*>(&uv.x);
        __half2 g1 = *reinterpret_cast<__half2*>(&uv.y);
        float2 e0 = __half22float2(g0);
        float2 e1 = __half22float2(g1);
        accV.x += e0.x * s; accV.y += e0.y * s;
        accV.z += e1.x * s; accV.w += e1.y * s;
    }
}

__global__ void aggregate_kernel() {
    int warp = (blockIdx.x * blockDim.x + threadIdx.x) >> 5;
    int lane = threadIdx.x & 31;
    if (warp >= N_NODES) return;
    int beg = g_off[warp];
    int deg = g_deg[warp];

    float4 accA = make_float4(0.f, 0.f, 0.f, 0.f);
    float4 accV = make_float4(0.f, 0.f, 0.f, 0.f);

    for (int base = 0; base < deg; base += 32) {
        int4 r = make_int4(0, 0, 0, 0);
        if (base + lane < deg) r = g_csr[beg + base + lane];
        int m = min(32, deg - base);
        for (int i = 0; i < m; i += 8) {
            uint2 UA[8], UV[8];
            float S[8];
            #pragma unroll
            for (int u = 0; u < 8; u++) {
                int j = i + u;
                int jj = (j < m) ? j : i;          // clamp: slot i always valid
                int a = __shfl_sync(0xFFFFFFFFu, r.y, jj);
                int v = __shfl_sync(0xFFFFFFFFu, r.z, jj);
                float s = __int_as_float(__shfl_sync(0xFFFFFFFFu, r.w, jj));
                S[u]  = (j < m) ? s : 0.f;
                UA[u] = *reinterpret_cast<const uint2*>(g_attH + a * KD + lane * 4);
                UV[u] = (lane < 16)
                    ? *reinterpret_cast<const uint2*>(g_valH + v * VD + lane * 4)
                    : make_uint2(0u, 0u);
            }
            #pragma unroll
            for (int u = 0; u < 8; u++)
                acc_edge(UA[u], UV[u], S[u], lane, accA, accV);
        }
    }

    __half* dst = g_aggH + (size_t)warp * AGGD;
    __half2 a0 = __floats2half2_rn(accA.x, accA.y);
    __half2 a1 = __floats2half2_rn(accA.z, accA.w);
    uint2 pa;
    pa.x = *reinterpret_cast<unsigned*>(&a0);
    pa.y = *reinterpret_cast<unsigned*>(&a1);
    *reinterpret_cast<uint2*>(dst + lane * 4) = pa;
    if (lane < 16) {
        __half2 v0 = __floats2half2_rn(accV.x, accV.y);
        __half2 v1 = __floats2half2_rn(accV.z, accV.w);
        uint2 pv;
        pv.x = *reinterpret_cast<unsigned*>(&v0);
        pv.y = *reinterpret_cast<unsigned*>(&v1);
        *reinterpret_cast<uint2*>(dst + KD + lane * 4) = pv;
    }
}

// ======== node GEMM via wmma (HMMA): out = elu(aggH @ W / rowsum + ent) =====
// 256 threads = 8 warps; tile = 64 nodes x 128 cols; 2 CTAs/SM for overlap.
// A/W smem rows padded to 200 halves (400B == 4 mod 32 banks, conflict-free).
#define WM_THREADS 256
#define TILE_ROWS 64
#define N_TILES 1563                        // ceil(100000 / 64)
#define A_STRIDE 200                        // halves
#define D_STRIDE 132                        // floats
#define SM_A 0
#define A_BYTES (TILE_ROWS * A_STRIDE * 2)  // 25600
#define SM_W A_BYTES
#define W_BYTES (KD * A_STRIDE * 2)         // 51200
#define SM_DST (SM_W + W_BYTES)             // 76800
#define WM_SMEM_TOTAL (SM_DST + TILE_ROWS * D_STRIDE * 4)   // 110592

__global__ void __launch_bounds__(WM_THREADS, 2)
node_wmma_kernel(const float* __restrict__ ent, float* __restrict__ out) {
    extern __shared__ char smem[];
    __half* As = reinterpret_cast<__half*>(smem + SM_A);
    __half* Ws = reinterpret_cast<__half*>(smem + SM_W);
    float*  Ds = reinterpret_cast<float*>(smem + SM_DST);

    int tid = threadIdx.x;
    int wid = tid >> 5;
    int rg  = wid >> 1;     // row group 0..3
    int ch  = wid & 1;      // col half 0..1

    // Wt once per block: 128 rows x 24 uint4, padded stride 25 uint4
    for (int i = tid; i < 128 * 24; i += WM_THREADS) {
        int row = i / 24;
        int off = i % 24;
        reinterpret_cast<uint4*>(Ws + row * A_STRIDE)[off] =
            __ldg(&reinterpret_cast<const uint4*>(g_Wt)[row * 24 + off]);
    }

    const float4* ent4 = reinterpret_cast<const float4*>(ent);
    float4* out4 = reinterpret_cast<float4*>(out);

    for (int tile = blockIdx.x; tile < N_TILES; tile += gridDim.x) {
        __syncthreads();   // As/Ds safe to overwrite (prev iter consumed)
        // stage A: 64 rows x 24 uint4 (padded rows)
        for (int i = tid; i < TILE_ROWS * 24; i += WM_THREADS) {
            int row = i / 24;
            int off = i % 24;
            int node = tile * TILE_ROWS + row;
            uint4 v = make_uint4(0u, 0u, 0u, 0u);
            if (node < N_NODES)
                v = __ldg(reinterpret_cast<const uint4*>(
                        g_aggH + (size_t)node * AGGD) + off);
            reinterpret_cast<uint4*>(As + row * A_STRIDE)[off] = v;
        }
        __syncthreads();

        wmma::fragment<wmma::accumulator, 16, 16, 16, float> acc[4];
        #pragma unroll
        for (int n = 0; n < 4; n++) wmma::fill_fragment(acc[n], 0.f);

        #pragma unroll
        for (int k = 0; k < AGGD; k += 16) {
            wmma::fragment<wmma::matrix_a, 16, 16, 16, __half, wmma::row_major> a;
            wmma::load_matrix_sync(a, As + rg * 16 * A_STRIDE + k, A_STRIDE);
            #pragma unroll
            for (int n = 0; n < 4; n++) {
                wmma::fragment<wmma::matrix_b, 16, 16, 16, __half, wmma::col_major> b;
                wmma::load_matrix_sync(b, Ws + (ch * 64 + n * 16) * A_STRIDE + k,
                                       A_STRIDE);
                wmma::mma_sync(acc[n], a, b, acc[n]);
            }
        }

        #pragma unroll
        for (int n = 0; n < 4; n++)
            wmma::store_matrix_sync(Ds + rg * 16 * D_STRIDE + ch * 64 + n * 16,
                                    acc[n], D_STRIDE, wmma::mem_row_major);
        __syncthreads();

        // coalesced epilogue: 64 rows x 32 float4 = 2048 units, 8 per thread
        #pragma unroll
        for (int it = 0; it < 8; it++) {
            int idx = tid + it * WM_THREADS;   // 0..2047
            int row = idx >> 5;
            int cg  = idx & 31;
            int node = tile * TILE_ROWS + row;
            if (node < N_NODES) {
                float4 dv = *reinterpret_cast<const float4*>(
                    Ds + row * D_STRIDE + cg * 4);
                float rs = g_rowsum[node];
                float inv = rs > 0.f ? 1.f / rs : 0.f;
                float4 e = __ldg(&ent4[node * 32 + cg]);
                float t0 = dv.x * inv + e.x;
                float t1 = dv.y * inv + e.y;
                float t2 = dv.z * inv + e.z;
                float t3 = dv.w * inv + e.w;
                float4 o;
                o.x = t0 > 0.f ? t0 : expm1f(t0);   // elu, alpha=1
                o.y = t1 > 0.f ? t1 : expm1f(t1);
                o.z = t2 > 0.f ? t2 : expm1f(t2);
                o.w = t3 > 0.f ? t3 : expm1f(t3);
                out4[node * 32 + cg] = o;
            }
        }
    }
}

// ---------------- launch ----------------------------------------------------
extern "C" void kernel_launch(void* const* d_in, const int* in_sizes, int n_in,
                              void* d_out, int out_size) {
    const void*  triples = d_in[0];                       // [1e6, 3] int64/int32
    const float* ent     = (const float*)d_in[1];         // [1e5, 128]
    const float* attf    = (const float*)d_in[2];         // [1e5, 128]
    const float* valf    = (const float*)d_in[3];         // [1e5, 64]
    const float* aw      = (const float*)d_in[4];         // [256]
    const float* ab      = (const float*)d_in[5];         // [1]
    const float* W       = (const float*)d_in[6];         // [192, 128]
    float* out           = (float*)d_out;                 // [1e5, 128]

    static bool init_done = false;
    static cudaStream_t s1;
    static cudaEvent_t ev_fork, ev_join;
    if (!init_done) {
        cudaFuncSetAttribute(node_wmma_kernel,
                             cudaFuncAttributeMaxDynamicSharedMemorySize,
                             WM_SMEM_TOTAL);
        cudaStreamCreateWithFlags(&s1, cudaStreamNonBlocking);
        cudaEventCreateWithFlags(&ev_fork, cudaEventDisableTiming);
        cudaEventCreateWithFlags(&ev_join, cudaEventDisableTiming);
        init_done = true;
    }

    // fork: branch B (score_pre + prepack) is independent of branch A
    cudaEventRecord(ev_fork, 0);
    cudaStreamWaitEvent(s1, ev_fork, 0);

    // branch B (stream s1): DRAM-heavy
    score_pre_kernel<<<(N_NODES + 7) / 8, 256, 0, s1>>>(ent, attf, aw);
    prepack_kernel<<<(KD * AGGD + 255) / 256, 256, 0, s1>>>(W);
    cudaEventRecord(ev_join, s1);

    // branch A (default stream): sniff -> resets -> deg -> scans
    sniff_kernel<<<1, 256>>>((const int*)triples);
    valconv_kernel<<<(N_NODES * VD / 4 + 255) / 256, 256>>>(valf);
    deg_kernel<<<(N_EDGES + 255) / 256, 256>>>((const int*)triples);
    scan_a_kernel<<<NBLK, 256>>>();
    scan_b_kernel<<<1, 512>>>();
    scan_c_kernel<<<NBLK, 256>>>();

    // join: score_fill needs sent/satt (B) and cursors (A)
    cudaStreamWaitEvent(0, ev_join, 0);
    score_fill_kernel<<<(N_EDGES + 255) / 256, 256>>>(triples, ab);
    aggregate_kernel<<<(N_NODES * 32 + 255) / 256, 256>>>();
    node_wmma_kernel<<<296, WM_THREADS, WM_SMEM_TOTAL>>>(ent, out);
}

// round 14
// speedup vs baseline: 1.0312x; 1.0312x over previous
#include <cuda_runtime.h>
#include <cuda_fp16.h>
#include <mma.h>
#include <math.h>
#include <cstdint>

using namespace nvcuda;

#define N_NODES 100000
#define N_EDGES 1000000
#define KD 128
#define VD 64
#define AGGD 192   // KD + VD
#define NBLK 391   // ceil(N_NODES / 256)

// ---------------- scratch (static device allocations, graph-safe) ----------
__device__ __align__(16) int2   g_csr8[N_EDGES];     // CSR-ordered {a, v}
__device__ __align__(16) __half g_attH[N_NODES * KD];
__device__ __align__(16) __half g_valH[N_NODES * VD];
__device__ __align__(16) __half g_aggH[N_NODES * AGGD];  // normalized fp16 rows
__device__ __align__(16) __half g_Wt[KD * AGGD];         // Wt[n][k] = W[k][n]
__device__ float g_sent[N_NODES];
__device__ float g_satt[N_NODES];
__device__ int   g_deg[N_NODES];
__device__ int   g_off[N_NODES];
__device__ int   g_cursor[N_NODES];
__device__ int   g_bsum[NBLK];
__device__ int   g_boff[NBLK];
__device__ int   g_idx64;

// ---------------- dtype sniff: int64 vs int32 triples (parallel) -----------
__global__ void sniff_kernel(const int* tri32) {
    int t = threadIdx.x;
    int bad = (tri32[2 * t + 1] != 0) ? 1 : 0;
    int any = __syncthreads_or(bad);
    if (t == 0) g_idx64 = any ? 0 : 1;
}

// ------- val fp16 conversion + per-node counter resets ----------------------
__global__ void valconv_kernel(const float* __restrict__ valf) {
    int i = blockIdx.x * blockDim.x + threadIdx.x;
    if (i < N_NODES) g_deg[i] = 0;
    int n4 = N_NODES * VD / 4;
    if (i >= n4) return;
    float4 v = reinterpret_cast<const float4*>(valf)[i];
    __half2 h0 = __floats2half2_rn(v.x, v.y);
    __half2 h1 = __floats2half2_rn(v.z, v.w);
    uint2 packed;
    packed.x = *reinterpret_cast<unsigned*>(&h0);
    packed.y = *reinterpret_cast<unsigned*>(&h1);
    *reinterpret_cast<uint2*>(g_valH + i * 4) = packed;
}

// ---------------- prepack W^T as fp16: Wt[n][k] = W[k][n] -------------------
__global__ void prepack_kernel(const float* __restrict__ W) {
    int idx = blockIdx.x * blockDim.x + threadIdx.x;
    if (idx >= KD * AGGD) return;
    int n = idx / AGGD;        // 0..127
    int k = idx % AGGD;        // 0..191
    g_Wt[idx] = __float2half_rn(W[k * KD + n]);
}

// ---------------- degree histogram (h column only) ---------------------------
__global__ void deg_kernel(const int* __restrict__ tri32) {
    int e = blockIdx.x * blockDim.x + threadIdx.x;
    if (e >= N_EDGES) return;
    int h = g_idx64 ? tri32[6 * e] : tri32[3 * e];
    atomicAdd(&g_deg[h], 1);
}

// ------- per-node score pre-reduction + att fp16 conversion ----------------
__global__ void score_pre_kernel(const float* __restrict__ ent,
                                 const float* __restrict__ att,
                                 const float* __restrict__ aw) {
    int warp = (blockIdx.x * blockDim.x + threadIdx.x) >> 5;
    int lane = threadIdx.x & 31;
    if (warp >= N_NODES) return;

    const float4* ent4 = reinterpret_cast<const float4*>(ent);
    const float4* att4 = reinterpret_cast<const float4*>(att);
    const float4* aw4  = reinterpret_cast<const float4*>(aw);

    float4 e = ent4[warp * 32 + lane];
    float4 a = att4[warp * 32 + lane];
    float4 we = __ldg(&aw4[lane]);
    float4 wa = __ldg(&aw4[32 + lane]);

    __half2 h0 = __floats2half2_rn(a.x, a.y);
    __half2 h1 = __floats2half2_rn(a.z, a.w);
    uint2 packed;
    packed.x = *reinterpret_cast<unsigned*>(&h0);
    packed.y = *reinterpret_cast<unsigned*>(&h1);
    *reinterpret_cast<uint2*>(g_attH + warp * KD + lane * 4) = packed;

    float se = e.x * we.x + e.y * we.y + e.z * we.z + e.w * we.w;
    float sa = a.x * wa.x + a.y * wa.y + a.z * wa.z + a.w * wa.w;
    #pragma unroll
    for (int o = 16; o; o >>= 1) {
        se += __shfl_xor_sync(0xFFFFFFFFu, se, o);
        sa += __shfl_xor_sync(0xFFFFFFFFu, sa, o);
    }
    if (lane == 0) {
        g_sent[warp] = se;
        g_satt[warp] = sa;
    }
}

// ---------------- 3-phase exclusive scan over degrees -----------------------
__global__ void scan_a_kernel() {
    __shared__ int sh[256];
    int t = threadIdx.x, b = blockIdx.x;
    int node = b * 256 + t;
    sh[t] = (node < N_NODES) ? g_deg[node] : 0;
    __syncthreads();
    #pragma unroll
    for (int d = 128; d; d >>= 1) {
        if (t < d) sh[t] += sh[t + d];
        __syncthreads();
    }
    if (t == 0) g_bsum[b] = sh[0];
}

__global__ void scan_b_kernel() {
    __shared__ int sh[512];
    int t = threadIdx.x;
    int v = (t < NBLK) ? g_bsum[t] : 0;
    sh[t] = v;
    __syncthreads();
    #pragma unroll
    for (int d = 1; d < 512; d <<= 1) {
        int x = (t >= d) ? sh[t - d] : 0;
        __syncthreads();
        sh[t] += x;
        __syncthreads();
    }
    if (t < NBLK) g_boff[t] = sh[t] - v;   // exclusive
}

__global__ void scan_c_kernel() {
    __shared__ int sh[256];
    int t = threadIdx.x, b = blockIdx.x;
    int node = b * 256 + t;
    int v = (node < N_NODES) ? g_deg[node] : 0;
    sh[t] = v;
    __syncthreads();
    #pragma unroll
    for (int d = 1; d < 256; d <<= 1) {
        int x = (t >= d) ? sh[t - d] : 0;
        __syncthreads();
        sh[t] += x;
        __syncthreads();
    }
    if (node < N_NODES) {
        int off = g_boff[b] + sh[t] - v;
        g_off[node] = off;
        g_cursor[node] = off;
    }
}

// ---------------- CSR permute: {a, v} only (no score) ------------------------
__global__ void fill_kernel(const void* __restrict__ tri) {
    int e = blockIdx.x * blockDim.x + threadIdx.x;
    if (e >= N_EDGES) return;
    int h, a, v;
    if (g_idx64) {
        const long long* t = reinterpret_cast<const long long*>(tri) + 3LL * e;
        h = (int)t[0]; a = (int)t[1]; v = (int)t[2];
    } else {
        const int* t = reinterpret_cast<const int*>(tri) + 3 * e;
        h = t[0]; a = t[1]; v = t[2];
    }
    int pos = atomicAdd(&g_cursor[h], 1);
    g_csr8[pos] = make_int2(a, v);
}

// ------- aggregate: inline scoring + softmax-normalized fp16 rows ------------
__device__ __forceinline__ void acc_edge(uint2 ua, uint2 uv, float s, int lane,
                                         float4& accA, float4& accV) {
    __half2 h0 = *reinterpret_cast<__half2*>(&ua.x);
    __half2 h1 = *reinterpret_cast<__half2*>(&ua.y);
    float2 f0 = __half22float2(h0);
    float2 f1 = __half22float2(h1);
    accA.x += f0.x * s; accA.y += f0.y * s;
    accA.z += f1.x * s; accA.w += f1.y * s;
    if (lane < 16) {
        __half2 g0 = *reinterpret_cast<__half2*>(&uv.x);
        __half2 g1 = *reinterpret_cast<__half2*>(&uv.y);
        float2 e0 = __half22float2(g0);
        float2 e1 = __half22float2(g1);
        accV.x += e0.x * s; accV.y += e0.y * s;
        accV.z += e1.x * s; accV.w += e1.y * s;
    }
}

__global__ void aggregate_kernel(const float* __restrict__ ab) {
    int warp = (blockIdx.x * blockDim.x + threadIdx.x) >> 5;
    int lane = threadIdx.x & 31;
    if (warp >= N_NODES) return;
    int beg = g_off[warp];
    int deg = g_deg[warp];

    float sent_h = g_sent[warp] + __ldg(&ab[0]);   // uniform for the warp

    float4 accA = make_float4(0.f, 0.f, 0.f, 0.f);
    float4 accV = make_float4(0.f, 0.f, 0.f, 0.f);
    float rs_acc = 0.f;

    for (int base = 0; base < deg; base += 32) {
        int2 r = make_int2(0, 0);
        float s_lane = 0.f;
        if (base + lane < deg) {
            r = g_csr8[beg + base + lane];
            float s = sent_h + g_satt[r.x];
            s = s > 0.f ? s : 0.2f * s;            // leaky_relu(0.2)
            s_lane = __expf(s);
        }
        rs_acc += s_lane;
        int m = min(32, deg - base);
        for (int i = 0; i < m; i += 8) {
            uint2 UA[8], UV[8];
            float S[8];
            #pragma unroll
            for (int u = 0; u < 8; u++) {
                int j = i + u;
                int jj = (j < m) ? j : i;          // clamp: slot i always valid
                int a = __shfl_sync(0xFFFFFFFFu, r.x, jj);
                int v = __shfl_sync(0xFFFFFFFFu, r.y, jj);
                float s = __shfl_sync(0xFFFFFFFFu, s_lane, jj);
                S[u]  = (j < m) ? s : 0.f;
                UA[u] = *reinterpret_cast<const uint2*>(g_attH + a * KD + lane * 4);
                UV[u] = (lane < 16)
                    ? *reinterpret_cast<const uint2*>(g_valH + v * VD + lane * 4)
                    : make_uint2(0u, 0u);
            }
            #pragma unroll
            for (int u = 0; u < 8; u++)
                acc_edge(UA[u], UV[u], S[u], lane, accA, accV);
        }
    }

    // warp-reduce rowsum, fold 1/rowsum into the stored row
    #pragma unroll
    for (int o = 16; o; o >>= 1)
        rs_acc += __shfl_xor_sync(0xFFFFFFFFu, rs_acc, o);
    float inv = rs_acc > 0.f ? 1.f / rs_acc : 0.f;

    __half* dst = g_aggH + (size_t)warp * AGGD;
    __half2 a0 = __floats2half2_rn(accA.x * inv, accA.y * inv);
    __half2 a1 = __floats2half2_rn(accA.z * inv, accA.w * inv);
    uint2 pa;
    pa.x = *reinterpret_cast<unsigned*>(&a0);
    pa.y = *reinterpret_cast<unsigned*>(&a1);
    *reinterpret_cast<uint2*>(dst + lane * 4) = pa;
    if (lane < 16) {
        __half2 v0 = __floats2half2_rn(accV.x * inv, accV.y * inv);
        __half2 v1 = __floats2half2_rn(accV.z * inv, accV.w * inv);
        uint2 pv;
        pv.x = *reinterpret_cast<unsigned*>(&v0);
        pv.y = *reinterpret_cast<unsigned*>(&v1);
        *reinterpret_cast<uint2*>(dst + KD + lane * 4) = pv;
    }
}

// ======== node GEMM via wmma (HMMA): out = elu(aggH @ W + ent) ==============
// 256 threads = 8 warps; tile = 64 nodes x 128 cols; 2 CTAs/SM for overlap.
// A/W smem rows padded to 200 halves (400B == 4 mod 32 banks, conflict-free).
#define WM_THREADS 256
#define TILE_ROWS 64
#define N_TILES 1563                        // ceil(100000 / 64)
#define A_STRIDE 200                        // halves
#define D_STRIDE 132                        // floats
#define SM_A 0
#define A_BYTES (TILE_ROWS * A_STRIDE * 2)  // 25600
#define SM_W A_BYTES
#define W_BYTES (KD * A_STRIDE * 2)         // 51200
#define SM_DST (SM_W + W_BYTES)             // 76800
#define WM_SMEM_TOTAL (SM_DST + TILE_ROWS * D_STRIDE * 4)   // 110592

__global__ void __launch_bounds__(WM_THREADS, 2)
node_wmma_kernel(const float* __restrict__ ent, float* __restrict__ out) {
    extern __shared__ char smem[];
    __half* As = reinterpret_cast<__half*>(smem + SM_A);
    __half* Ws = reinterpret_cast<__half*>(smem + SM_W);
    float*  Ds = reinterpret_cast<float*>(smem + SM_DST);

    int tid = threadIdx.x;
    int wid = tid >> 5;
    int rg  = wid >> 1;     // row group 0..3
    int ch  = wid & 1;      // col half 0..1

    // Wt once per block: 128 rows x 24 uint4, padded stride 25 uint4
    for (int i = tid; i < 128 * 24; i += WM_THREADS) {
        int row = i / 24;
        int off = i % 24;
        reinterpret_cast<uint4*>(Ws + row * A_STRIDE)[off] =
            __ldg(&reinterpret_cast<const uint4*>(g_Wt)[row * 24 + off]);
    }

    const float4* ent4 = reinterpret_cast<const float4*>(ent);
    float4* out4 = reinterpret_cast<float4*>(out);

    for (int tile = blockIdx.x; tile < N_TILES; tile += gridDim.x) {
        __syncthreads();   // As/Ds safe to overwrite (prev iter consumed)
        // stage A: 64 rows x 24 uint4 (padded rows)
        for (int i = tid; i < TILE_ROWS * 24; i += WM_THREADS) {
            int row = i / 24;
            int off = i % 24;
            int node = tile * TILE_ROWS + row;
            uint4 v = make_uint4(0u, 0u, 0u, 0u);
            if (node < N_NODES)
                v = __ldg(reinterpret_cast<const uint4*>(
                        g_aggH + (size_t)node * AGGD) + off);
            reinterpret_cast<uint4*>(As + row * A_STRIDE)[off] = v;
        }
        __syncthreads();

        wmma::fragment<wmma::accumulator, 16, 16, 16, float> acc[4];
        #pragma unroll
        for (int n = 0; n < 4; n++) wmma::fill_fragment(acc[n], 0.f);

        #pragma unroll
        for (int k = 0; k < AGGD; k += 16) {
            wmma::fragment<wmma::matrix_a, 16, 16, 16, __half, wmma::row_major> a;
            wmma::load_matrix_sync(a, As + rg * 16 * A_STRIDE + k, A_STRIDE);
            #pragma unroll
            for (int n = 0; n < 4; n++) {
                wmma::fragment<wmma::matrix_b, 16, 16, 16, __half, wmma::col_major> b;
                wmma::load_matrix_sync(b, Ws + (ch * 64 + n * 16) * A_STRIDE + k,
                                       A_STRIDE);
                wmma::mma_sync(acc[n], a, b, acc[n]);
            }
        }

        #pragma unroll
        for (int n = 0; n < 4; n++)
            wmma::store_matrix_sync(Ds + rg * 16 * D_STRIDE + ch * 64 + n * 16,
                                    acc[n], D_STRIDE, wmma::mem_row_major);
        __syncthreads();

        // coalesced epilogue: out = elu(D + ent)
        #pragma unroll
        for (int it = 0; it < 8; it++) {
            int idx = tid + it * WM_THREADS;   // 0..2047
            int row = idx >> 5;
            int cg  = idx & 31;
            int node = tile * TILE_ROWS + row;
            if (node < N_NODES) {
                float4 dv = *reinterpret_cast<const float4*>(
                    Ds + row * D_STRIDE + cg * 4);
                float4 e = __ldg(&ent4[node * 32 + cg]);
                float t0 = dv.x + e.x;
                float t1 = dv.y + e.y;
                float t2 = dv.z + e.z;
                float t3 = dv.w + e.w;
                float4 o;
                o.x = t0 > 0.f ? t0 : expm1f(t0);   // elu, alpha=1
                o.y = t1 > 0.f ? t1 : expm1f(t1);
                o.z = t2 > 0.f ? t2 : expm1f(t2);
                o.w = t3 > 0.f ? t3 : expm1f(t3);
                out4[node * 32 + cg] = o;
            }
        }
    }
}

// ---------------- launch ----------------------------------------------------
extern "C" void kernel_launch(void* const* d_in, const int* in_sizes, int n_in,
                              void* d_out, int out_size) {
    const void*  triples = d_in[0];                       // [1e6, 3] int64/int32
    const float* ent     = (const float*)d_in[1];         // [1e5, 128]
    const float* attf    = (const float*)d_in[2];         // [1e5, 128]
    const float* valf    = (const float*)d_in[3];         // [1e5, 64]
    const float* aw      = (const float*)d_in[4];         // [256]
    const float* ab      = (const float*)d_in[5];         // [1]
    const float* W       = (const float*)d_in[6];         // [192, 128]
    float* out           = (float*)d_out;                 // [1e5, 128]

    static bool init_done = false;
    static cudaStream_t s1;
    static cudaEvent_t ev_fork, ev_join;
    if (!init_done) {
        cudaFuncSetAttribute(node_wmma_kernel,
                             cudaFuncAttributeMaxDynamicSharedMemorySize,
                             WM_SMEM_TOTAL);
        cudaStreamCreateWithFlags(&s1, cudaStreamNonBlocking);
        cudaEventCreateWithFlags(&ev_fork, cudaEventDisableTiming);
        cudaEventCreateWithFlags(&ev_join, cudaEventDisableTiming);
        init_done = true;
    }

    // fork: branch B (score_pre + prepack) only needed by aggregate/node_wmma
    cudaEventRecord(ev_fork, 0);
    cudaStreamWaitEvent(s1, ev_fork, 0);

    // branch B (stream s1): DRAM-heavy, fully hidden under branch A
    score_pre_kernel<<<(N_NODES + 7) / 8, 256, 0, s1>>>(ent, attf, aw);
    prepack_kernel<<<(KD * AGGD + 255) / 256, 256, 0, s1>>>(W);
    cudaEventRecord(ev_join, s1);

    // branch A (default stream): sniff -> resets -> deg -> scans -> fill
    sniff_kernel<<<1, 256>>>((const int*)triples);
    valconv_kernel<<<(N_NODES * VD / 4 + 255) / 256, 256>>>(valf);
    deg_kernel<<<(N_EDGES + 255) / 256, 256>>>((const int*)triples);
    scan_a_kernel<<<NBLK, 256>>>();
    scan_b_kernel<<<1, 512>>>();
    scan_c_kernel<<<NBLK, 256>>>();
    fill_kernel<<<(N_EDGES + 255) / 256, 256>>>(triples);

    // join: aggregate needs sent/satt (B) and CSR (A)
    cudaStreamWaitEvent(0, ev_join, 0);
    aggregate_kernel<<<(N_NODES * 32 + 255) / 256, 256>>>(ab);
    node_wmma_kernel<<<296, WM_THREADS, WM_SMEM_TOTAL>>>(ent, out);
}

// round 15
// speedup vs baseline: 1.1062x; 1.0728x over previous
#include <cuda_runtime.h>
#include <cuda_fp16.h>
#include <mma.h>
#include <math.h>
#include <cstdint>

using namespace nvcuda;

#define N_NODES 100000
#define N_EDGES 1000000
#define KD 128
#define VD 64
#define NBLK 391   // ceil(N_NODES / 256)

// ---------------- scratch (static device allocations, graph-safe) ----------
__device__ __align__(16) int2   g_csr8[N_EDGES];         // CSR-ordered {a, v}
__device__ __align__(16) __half g_attP[N_NODES * KD];    // att @ W[0:128]
__device__ __align__(16) __half g_valP[N_NODES * KD];    // val @ W[128:192]
__device__ float g_sent[N_NODES];
__device__ float g_satt[N_NODES];
__device__ int   g_deg[N_NODES];
__device__ int   g_off[N_NODES];
__device__ int   g_cursor[N_NODES];
__device__ int   g_bsum[NBLK];
__device__ int   g_boff[NBLK];
__device__ int   g_idx64;

// ------- dtype sniff (block 0) + deg reset (all blocks) ---------------------
__global__ void sniff_reset_kernel(const int* tri32) {
    int i = blockIdx.x * 256 + threadIdx.x;
    if (i < N_NODES) g_deg[i] = 0;
    if (blockIdx.x == 0) {
        int bad = (tri32[2 * threadIdx.x + 1] != 0) ? 1 : 0;
        int any = __syncthreads_or(bad);
        if (threadIdx.x == 0) g_idx64 = any ? 0 : 1;
    }
}

// ------- per-node score pre-reduction ----------------------------------------
__global__ void score_pre_kernel(const float* __restrict__ ent,
                                 const float* __restrict__ att,
                                 const float* __restrict__ aw) {
    int warp = (blockIdx.x * blockDim.x + threadIdx.x) >> 5;
    int lane = threadIdx.x & 31;
    if (warp >= N_NODES) return;

    const float4* ent4 = reinterpret_cast<const float4*>(ent);
    const float4* att4 = reinterpret_cast<const float4*>(att);
    const float4* aw4  = reinterpret_cast<const float4*>(aw);

    float4 e = ent4[warp * 32 + lane];
    float4 a = att4[warp * 32 + lane];
    float4 we = __ldg(&aw4[lane]);
    float4 wa = __ldg(&aw4[32 + lane]);

    float se = e.x * we.x + e.y * we.y + e.z * we.z + e.w * we.w;
    float sa = a.x * wa.x + a.y * wa.y + a.z * wa.z + a.w * wa.w;
    #pragma unroll
    for (int o = 16; o; o >>= 1) {
        se += __shfl_xor_sync(0xFFFFFFFFu, se, o);
        sa += __shfl_xor_sync(0xFFFFFFFFu, sa, o);
    }
    if (lane == 0) {
        g_sent[warp] = se;
        g_satt[warp] = sa;
    }
}

// ======== projection GEMM via wmma: dst = fp16(src[N,K] @ W[woff:woff+K]) ===
// 256 thr, 8 warps, tile 64 rows x 128 cols, persistent grid; 2 CTAs/SM.
// smem strides padded to K+8 halves (== 4 mod 32 fp32 banks: conflict-free).
#define PROJ_TILES 1563                     // ceil(100000 / 64)

template <int K>
__global__ void __launch_bounds__(256, 2)
proj_kernel(const float* __restrict__ src, const float* __restrict__ W,
            __half* __restrict__ dst, int woff) {
    constexpr int STRIDE = K + 8;           // halves
    constexpr int AS_HALVES = 64 * STRIDE;
    constexpr int WS_HALVES = 128 * STRIDE;
    extern __shared__ char smem[];
    __half* As = reinterpret_cast<__half*>(smem);
    __half* Ws = As + AS_HALVES;
    float*  Ds = reinterpret_cast<float*>(Ws + WS_HALVES);   // [64][132]

    int tid = threadIdx.x;
    int wid = tid >> 5;
    int rg  = wid >> 1;     // row group 0..3 (16 rows each)
    int ch  = wid & 1;      // col half 0..1 (64 cols each)

    // stage Wt: Ws[n][k] = W[(woff+k)*128 + n]  (once per CTA, L2-cached)
    for (int i = tid; i < 128 * K; i += 256) {
        int n = i / K;
        int k = i % K;
        Ws[n * STRIDE + k] = __float2half_rn(__ldg(&W[(woff + k) * KD + n]));
    }

    for (int tile = blockIdx.x; tile < PROJ_TILES; tile += gridDim.x) {
        __syncthreads();
        // stage A (fp32 -> fp16): 64 rows x K/4 float4
        for (int i = tid; i < 64 * (K / 4); i += 256) {
            int row = i / (K / 4);
            int f4  = i % (K / 4);
            int node = tile * 64 + row;
            float4 v = (node < N_NODES)
                ? __ldg(reinterpret_cast<const float4*>(src + (size_t)node * K) + f4)
                : make_float4(0.f, 0.f, 0.f, 0.f);
            __half2 h0 = __floats2half2_rn(v.x, v.y);
            __half2 h1 = __floats2half2_rn(v.z, v.w);
            uint2 p;
            p.x = *reinterpret_cast<unsigned*>(&h0);
            p.y = *reinterpret_cast<unsigned*>(&h1);
            *reinterpret_cast<uint2*>(As + row * STRIDE + f4 * 4) = p;
        }
        __syncthreads();

        wmma::fragment<wmma::accumulator, 16, 16, 16, float> acc[4];
        #pragma unroll
        for (int n = 0; n < 4; n++) wmma::fill_fragment(acc[n], 0.f);

        #pragma unroll
        for (int k0 = 0; k0 < K; k0 += 16) {
            wmma::fragment<wmma::matrix_a, 16, 16, 16, __half, wmma::row_major> a;
            wmma::load_matrix_sync(a, As + rg * 16 * STRIDE + k0, STRIDE);
            #pragma unroll
            for (int n = 0; n < 4; n++) {
                wmma::fragment<wmma::matrix_b, 16, 16, 16, __half, wmma::col_major> b;
                wmma::load_matrix_sync(b, Ws + (ch * 64 + n * 16) * STRIDE + k0,
                                       STRIDE);
                wmma::mma_sync(acc[n], a, b, acc[n]);
            }
        }

        #pragma unroll
        for (int n = 0; n < 4; n++)
            wmma::store_matrix_sync(Ds + rg * 16 * 132 + ch * 64 + n * 16,
                                    acc[n], 132, wmma::mem_row_major);
        __syncthreads();

        // fp16 pack + coalesced store: 64 rows x 64 half2
        for (int idx = tid; idx < 64 * 64; idx += 256) {
            int row = idx >> 6;
            int c2  = idx & 63;
            int node = tile * 64 + row;
            if (node < N_NODES) {
                float lo = Ds[row * 132 + c2 * 2];
                float hi = Ds[row * 132 + c2 * 2 + 1];
                __half2 h = __floats2half2_rn(lo, hi);
                *reinterpret_cast<unsigned*>(dst + (size_t)node * KD + c2 * 2) =
                    *reinterpret_cast<unsigned*>(&h);
            }
        }
    }
}

// ---------------- degree histogram (h column only) ---------------------------
__global__ void deg_kernel(const int* __restrict__ tri32) {
    int e = blockIdx.x * blockDim.x + threadIdx.x;
    if (e >= N_EDGES) return;
    int h = g_idx64 ? tri32[6 * e] : tri32[3 * e];
    atomicAdd(&g_deg[h], 1);
}

// ---------------- 3-phase exclusive scan over degrees -----------------------
__global__ void scan_a_kernel() {
    __shared__ int sh[256];
    int t = threadIdx.x, b = blockIdx.x;
    int node = b * 256 + t;
    sh[t] = (node < N_NODES) ? g_deg[node] : 0;
    __syncthreads();
    #pragma unroll
    for (int d = 128; d; d >>= 1) {
        if (t < d) sh[t] += sh[t + d];
        __syncthreads();
    }
    if (t == 0) g_bsum[b] = sh[0];
}

__global__ void scan_b_kernel() {
    __shared__ int sh[512];
    int t = threadIdx.x;
    int v = (t < NBLK) ? g_bsum[t] : 0;
    sh[t] = v;
    __syncthreads();
    #pragma unroll
    for (int d = 1; d < 512; d <<= 1) {
        int x = (t >= d) ? sh[t - d] : 0;
        __syncthreads();
        sh[t] += x;
        __syncthreads();
    }
    if (t < NBLK) g_boff[t] = sh[t] - v;   // exclusive
}

__global__ void scan_c_kernel() {
    __shared__ int sh[256];
    int t = threadIdx.x, b = blockIdx.x;
    int node = b * 256 + t;
    int v = (node < N_NODES) ? g_deg[node] : 0;
    sh[t] = v;
    __syncthreads();
    #pragma unroll
    for (int d = 1; d < 256; d <<= 1) {
        int x = (t >= d) ? sh[t - d] : 0;
        __syncthreads();
        sh[t] += x;
        __syncthreads();
    }
    if (node < N_NODES) {
        int off = g_boff[b] + sh[t] - v;
        g_off[node] = off;
        g_cursor[node] = off;
    }
}

// ---------------- CSR permute: {a, v} only ----------------------------------
__global__ void fill_kernel(const void* __restrict__ tri) {
    int e = blockIdx.x * blockDim.x + threadIdx.x;
    if (e >= N_EDGES) return;
    int h, a, v;
    if (g_idx64) {
        const long long* t = reinterpret_cast<const long long*>(tri) + 3LL * e;
        h = (int)t[0]; a = (int)t[1]; v = (int)t[2];
    } else {
        const int* t = reinterpret_cast<const int*>(tri) + 3 * e;
        h = t[0]; a = t[1]; v = t[2];
    }
    int pos = atomicAdd(&g_cursor[h], 1);
    g_csr8[pos] = make_int2(a, v);
}

// ------- FINAL aggregate: inline scoring + projected gathers + epilogue -----
// out[h] = elu( (sum_e s_e * (attP[a_e] + valP[v_e])) / rowsum + ent[h] )
__device__ __forceinline__ void acc_edge(uint2 ua, uint2 uv, float s,
                                         float4& acc) {
    __half2 p0 = __hadd2(*reinterpret_cast<__half2*>(&ua.x),
                         *reinterpret_cast<__half2*>(&uv.x));
    __half2 p1 = __hadd2(*reinterpret_cast<__half2*>(&ua.y),
                         *reinterpret_cast<__half2*>(&uv.y));
    float2 f0 = __half22float2(p0);
    float2 f1 = __half22float2(p1);
    acc.x += f0.x * s; acc.y += f0.y * s;
    acc.z += f1.x * s; acc.w += f1.y * s;
}

__global__ void aggregate_kernel(const float* __restrict__ ab,
                                 const float* __restrict__ ent,
                                 float* __restrict__ out) {
    int warp = (blockIdx.x * blockDim.x + threadIdx.x) >> 5;
    int lane = threadIdx.x & 31;
    if (warp >= N_NODES) return;
    int beg = g_off[warp];
    int deg = g_deg[warp];

    float sent_h = g_sent[warp] + __ldg(&ab[0]);   // uniform for the warp

    float4 acc = make_float4(0.f, 0.f, 0.f, 0.f);
    float rs_acc = 0.f;

    for (int base = 0; base < deg; base += 32) {
        int2 r = make_int2(0, 0);
        float s_lane = 0.f;
        if (base + lane < deg) {
            r = g_csr8[beg + base + lane];
            float s = sent_h + g_satt[r.x];
            s = s > 0.f ? s : 0.2f * s;            // leaky_relu(0.2)
            s_lane = __expf(s);
        }
        rs_acc += s_lane;
        int m = min(32, deg - base);
        for (int i = 0; i < m; i += 8) {
            uint2 UA[8], UV[8];
            float S[8];
            #pragma unroll
            for (int u = 0; u < 8; u++) {
                int j = i + u;
                int jj = (j < m) ? j : i;          // clamp: slot i always valid
                int a = __shfl_sync(0xFFFFFFFFu, r.x, jj);
                int v = __shfl_sync(0xFFFFFFFFu, r.y, jj);
                float s = __shfl_sync(0xFFFFFFFFu, s_lane, jj);
                S[u]  = (j < m) ? s : 0.f;
                UA[u] = *reinterpret_cast<const uint2*>(
                    g_attP + (size_t)a * KD + lane * 4);
                UV[u] = *reinterpret_cast<const uint2*>(
                    g_valP + (size_t)v * KD + lane * 4);
            }
            #pragma unroll
            for (int u = 0; u < 8; u++)
                acc_edge(UA[u], UV[u], S[u], acc);
        }
    }

    #pragma unroll
    for (int o = 16; o; o >>= 1)
        rs_acc += __shfl_xor_sync(0xFFFFFFFFu, rs_acc, o);
    float inv = rs_acc > 0.f ? 1.f / rs_acc : 0.f;

    float4 e = reinterpret_cast<const float4*>(ent)[warp * 32 + lane];
    float t0 = acc.x * inv + e.x;
    float t1 = acc.y * inv + e.y;
    float t2 = acc.z * inv + e.z;
    float t3 = acc.w * inv + e.w;
    float4 o;
    o.x = t0 > 0.f ? t0 : expm1f(t0);   // elu, alpha=1
    o.y = t1 > 0.f ? t1 : expm1f(t1);
    o.z = t2 > 0.f ? t2 : expm1f(t2);
    o.w = t3 > 0.f ? t3 : expm1f(t3);
    reinterpret_cast<float4*>(out)[warp * 32 + lane] = o;
}

// ---------------- launch ----------------------------------------------------
#define PROJ128_SMEM (64 * 136 * 2 + 128 * 136 * 2 + 64 * 132 * 4)   // 86016
#define PROJ64_SMEM  (64 * 72 * 2  + 128 * 72 * 2  + 64 * 132 * 4)   // 61440

extern "C" void kernel_launch(void* const* d_in, const int* in_sizes, int n_in,
                              void* d_out, int out_size) {
    const void*  triples = d_in[0];                       // [1e6, 3] int64/int32
    const float* ent     = (const float*)d_in[1];         // [1e5, 128]
    const float* attf    = (const float*)d_in[2];         // [1e5, 128]
    const float* valf    = (const float*)d_in[3];         // [1e5, 64]
    const float* aw      = (const float*)d_in[4];         // [256]
    const float* ab      = (const float*)d_in[5];         // [1]
    const float* W       = (const float*)d_in[6];         // [192, 128]
    float* out           = (float*)d_out;                 // [1e5, 128]

    static bool init_done = false;
    static cudaStream_t s1;
    static cudaEvent_t ev_fork, ev_join;
    if (!init_done) {
        cudaFuncSetAttribute(proj_kernel<128>,
                             cudaFuncAttributeMaxDynamicSharedMemorySize,
                             PROJ128_SMEM);
        cudaFuncSetAttribute(proj_kernel<64>,
                             cudaFuncAttributeMaxDynamicSharedMemorySize,
                             PROJ64_SMEM);
        cudaStreamCreateWithFlags(&s1, cudaStreamNonBlocking);
        cudaEventCreateWithFlags(&ev_fork, cudaEventDisableTiming);
        cudaEventCreateWithFlags(&ev_join, cudaEventDisableTiming);
        init_done = true;
    }

    __half* attP; cudaGetSymbolAddress((void**)&attP, g_attP);
    __half* valP; cudaGetSymbolAddress((void**)&valP, g_valP);

    // launch 1: sniff + deg reset (branch A head)
    sniff_reset_kernel<<<NBLK, 256>>>((const int*)triples);

    // fork: branch B (scores + projections) independent of triples chain
    cudaEventRecord(ev_fork, 0);
    cudaStreamWaitEvent(s1, ev_fork, 0);

    // branch B (stream s1): launches 2-4 (proj_val lands in the profile slot)
    score_pre_kernel<<<(N_NODES + 7) / 8, 256, 0, s1>>>(ent, attf, aw);
    proj_kernel<128><<<296, 256, PROJ128_SMEM, s1>>>(attf, W, attP, 0);
    proj_kernel<64><<<296, 256, PROJ64_SMEM, s1>>>(valf, W, valP, KD);
    cudaEventRecord(ev_join, s1);

    // branch A (default): deg -> scans -> fill
    deg_kernel<<<(N_EDGES + 255) / 256, 256>>>((const int*)triples);
    scan_a_kernel<<<NBLK, 256>>>();
    scan_b_kernel<<<1, 512>>>();
    scan_c_kernel<<<NBLK, 256>>>();
    fill_kernel<<<(N_EDGES + 255) / 256, 256>>>(triples);

    // join: aggregate needs sent/satt + projections (B) and CSR (A)
    cudaStreamWaitEvent(0, ev_join, 0);
    aggregate_kernel<<<(N_NODES * 32 + 255) / 256, 256>>>(ab, ent, out);
}

// round 16
// speedup vs baseline: 1.2386x; 1.1197x over previous
#include <cuda_runtime.h>
#include <cuda_fp16.h>
#include <mma.h>
#include <math.h>
#include <cstdint>

using namespace nvcuda;

#define N_NODES 100000
#define N_EDGES 1000000
#define KD 128
#define VD 64
#define WK 192     // W rows (K of the original GEMM)
#define NBLK 391   // ceil(N_NODES / 256)

// ---------------- scratch (static device allocations, graph-safe) ----------
__device__ __align__(16) int2   g_csr8[N_EDGES];         // CSR-ordered {a, v}
__device__ __align__(16) __half g_attP[N_NODES * KD];    // att @ W[0:128]
__device__ __align__(16) __half g_valP[N_NODES * KD];    // val @ W[128:192]
__device__ __align__(16) __half g_Wt[KD * WK];           // Wt[n][k] = W[k][n]
__device__ float g_sent[N_NODES];
__device__ float g_satt[N_NODES];
__device__ int   g_deg[N_NODES];
__device__ int   g_off[N_NODES];
__device__ int   g_cursor[N_NODES];
__device__ int   g_bsum[NBLK];
__device__ int   g_boff[NBLK];
__device__ int   g_idx64;

// ------- dtype sniff (block 0) + deg reset (all blocks) ---------------------
__global__ void sniff_reset_kernel(const int* tri32) {
    int i = blockIdx.x * 256 + threadIdx.x;
    if (i < N_NODES) g_deg[i] = 0;
    if (blockIdx.x == 0) {
        int bad = (tri32[2 * threadIdx.x + 1] != 0) ? 1 : 0;
        int any = __syncthreads_or(bad);
        if (threadIdx.x == 0) g_idx64 = any ? 0 : 1;
    }
}

// ---------------- prepack W^T as fp16: Wt[n][k] = W[k][n] (once) ------------
__global__ void prepack_kernel(const float* __restrict__ W) {
    int idx = blockIdx.x * blockDim.x + threadIdx.x;   // n fast -> coalesced read
    if (idx >= KD * WK) return;
    int k = idx / KD;
    int n = idx % KD;
    g_Wt[n * WK + k] = __float2half_rn(W[idx]);
}

// ------- per-node score pre-reduction ----------------------------------------
__global__ void score_pre_kernel(const float* __restrict__ ent,
                                 const float* __restrict__ att,
                                 const float* __restrict__ aw) {
    int warp = (blockIdx.x * blockDim.x + threadIdx.x) >> 5;
    int lane = threadIdx.x & 31;
    if (warp >= N_NODES) return;

    const float4* ent4 = reinterpret_cast<const float4*>(ent);
    const float4* att4 = reinterpret_cast<const float4*>(att);
    const float4* aw4  = reinterpret_cast<const float4*>(aw);

    float4 e = ent4[warp * 32 + lane];
    float4 a = att4[warp * 32 + lane];
    float4 we = __ldg(&aw4[lane]);
    float4 wa = __ldg(&aw4[32 + lane]);

    float se = e.x * we.x + e.y * we.y + e.z * we.z + e.w * we.w;
    float sa = a.x * wa.x + a.y * wa.y + a.z * wa.z + a.w * wa.w;
    #pragma unroll
    for (int o = 16; o; o >>= 1) {
        se += __shfl_xor_sync(0xFFFFFFFFu, se, o);
        sa += __shfl_xor_sync(0xFFFFFFFFu, sa, o);
    }
    if (lane == 0) {
        g_sent[warp] = se;
        g_satt[warp] = sa;
    }
}

// ======== projection GEMM via wmma: dst = fp16(src[N,K] @ W[woff:woff+K]) ===
// 256 thr, 8 warps, tile 64 rows x 128 cols, persistent grid; 2 CTAs/SM.
// Ws staged from prepacked g_Wt with coalesced uint4 copies.
// smem strides padded to K+8 halves (conflict-free fragment loads).
#define PROJ_TILES 1563                     // ceil(100000 / 64)

template <int K>
__global__ void __launch_bounds__(256, 2)
proj_kernel(const float* __restrict__ src, __half* __restrict__ dst, int woff) {
    constexpr int STRIDE = K + 8;           // halves
    constexpr int AS_HALVES = 64 * STRIDE;
    constexpr int WS_HALVES = 128 * STRIDE;
    extern __shared__ char smem[];
    __half* As = reinterpret_cast<__half*>(smem);
    __half* Ws = As + AS_HALVES;
    float*  Ds = reinterpret_cast<float*>(Ws + WS_HALVES);   // [64][132]

    int tid = threadIdx.x;
    int wid = tid >> 5;
    int rg  = wid >> 1;     // row group 0..3 (16 rows each)
    int ch  = wid & 1;      // col half 0..1 (64 cols each)

    // stage Ws[n][0..K) = g_Wt[n][woff..woff+K): coalesced uint4 (8 halves)
    for (int i = tid; i < 128 * (K / 8); i += 256) {
        int n   = i / (K / 8);
        int off = i % (K / 8);
        *reinterpret_cast<uint4*>(Ws + n * STRIDE + off * 8) =
            __ldg(reinterpret_cast<const uint4*>(g_Wt + n * WK + woff) + off);
    }

    for (int tile = blockIdx.x; tile < PROJ_TILES; tile += gridDim.x) {
        __syncthreads();
        // stage A (fp32 -> fp16): 64 rows x K/4 float4
        for (int i = tid; i < 64 * (K / 4); i += 256) {
            int row = i / (K / 4);
            int f4  = i % (K / 4);
            int node = tile * 64 + row;
            float4 v = (node < N_NODES)
                ? __ldg(reinterpret_cast<const float4*>(src + (size_t)node * K) + f4)
                : make_float4(0.f, 0.f, 0.f, 0.f);
            __half2 h0 = __floats2half2_rn(v.x, v.y);
            __half2 h1 = __floats2half2_rn(v.z, v.w);
            uint2 p;
            p.x = *reinterpret_cast<unsigned*>(&h0);
            p.y = *reinterpret_cast<unsigned*>(&h1);
            *reinterpret_cast<uint2*>(As + row * STRIDE + f4 * 4) = p;
        }
        __syncthreads();

        wmma::fragment<wmma::accumulator, 16, 16, 16, float> acc[4];
        #pragma unroll
        for (int n = 0; n < 4; n++) wmma::fill_fragment(acc[n], 0.f);

        #pragma unroll
        for (int k0 = 0; k0 < K; k0 += 16) {
            wmma::fragment<wmma::matrix_a, 16, 16, 16, __half, wmma::row_major> a;
            wmma::load_matrix_sync(a, As + rg * 16 * STRIDE + k0, STRIDE);
            #pragma unroll
            for (int n = 0; n < 4; n++) {
                wmma::fragment<wmma::matrix_b, 16, 16, 16, __half, wmma::col_major> b;
                wmma::load_matrix_sync(b, Ws + (ch * 64 + n * 16) * STRIDE + k0,
                                       STRIDE);
                wmma::mma_sync(acc[n], a, b, acc[n]);
            }
        }

        #pragma unroll
        for (int n = 0; n < 4; n++)
            wmma::store_matrix_sync(Ds + rg * 16 * 132 + ch * 64 + n * 16,
                                    acc[n], 132, wmma::mem_row_major);
        __syncthreads();

        // fp16 pack + coalesced store: 64 rows x 64 half2
        for (int idx = tid; idx < 64 * 64; idx += 256) {
            int row = idx >> 6;
            int c2  = idx & 63;
            int node = tile * 64 + row;
            if (node < N_NODES) {
                float lo = Ds[row * 132 + c2 * 2];
                float hi = Ds[row * 132 + c2 * 2 + 1];
                __half2 h = __floats2half2_rn(lo, hi);
                *reinterpret_cast<unsigned*>(dst + (size_t)node * KD + c2 * 2) =
                    *reinterpret_cast<unsigned*>(&h);
            }
        }
    }
}

// ---------------- degree histogram (h column only) ---------------------------
__global__ void deg_kernel(const int* __restrict__ tri32) {
    int e = blockIdx.x * blockDim.x + threadIdx.x;
    if (e >= N_EDGES) return;
    int h = g_idx64 ? tri32[6 * e] : tri32[3 * e];
    atomicAdd(&g_deg[h], 1);
}

// ---------------- 3-phase exclusive scan over degrees -----------------------
__global__ void scan_a_kernel() {
    __shared__ int sh[256];
    int t = threadIdx.x, b = blockIdx.x;
    int node = b * 256 + t;
    sh[t] = (node < N_NODES) ? g_deg[node] : 0;
    __syncthreads();
    #pragma unroll
    for (int d = 128; d; d >>= 1) {
        if (t < d) sh[t] += sh[t + d];
        __syncthreads();
    }
    if (t == 0) g_bsum[b] = sh[0];
}

__global__ void scan_b_kernel() {
    __shared__ int sh[512];
    int t = threadIdx.x;
    int v = (t < NBLK) ? g_bsum[t] : 0;
    sh[t] = v;
    __syncthreads();
    #pragma unroll
    for (int d = 1; d < 512; d <<= 1) {
        int x = (t >= d) ? sh[t - d] : 0;
        __syncthreads();
        sh[t] += x;
        __syncthreads();
    }
    if (t < NBLK) g_boff[t] = sh[t] - v;   // exclusive
}

__global__ void scan_c_kernel() {
    __shared__ int sh[256];
    int t = threadIdx.x, b = blockIdx.x;
    int node = b * 256 + t;
    int v = (node < N_NODES) ? g_deg[node] : 0;
    sh[t] = v;
    __syncthreads();
    #pragma unroll
    for (int d = 1; d < 256; d <<= 1) {
        int x = (t >= d) ? sh[t - d] : 0;
        __syncthreads();
        sh[t] += x;
        __syncthreads();
    }
    if (node < N_NODES) {
        int off = g_boff[b] + sh[t] - v;
        g_off[node] = off;
        g_cursor[node] = off;
    }
}

// ---------------- CSR permute: {a, v} only ----------------------------------
__global__ void fill_kernel(const void* __restrict__ tri) {
    int e = blockIdx.x * blockDim.x + threadIdx.x;
    if (e >= N_EDGES) return;
    int h, a, v;
    if (g_idx64) {
        const long long* t = reinterpret_cast<const long long*>(tri) + 3LL * e;
        h = (int)t[0]; a = (int)t[1]; v = (int)t[2];
    } else {
        const int* t = reinterpret_cast<const int*>(tri) + 3 * e;
        h = t[0]; a = t[1]; v = t[2];
    }
    int pos = atomicAdd(&g_cursor[h], 1);
    g_csr8[pos] = make_int2(a, v);
}

// ------- FINAL aggregate: inline scoring + projected gathers + epilogue -----
__device__ __forceinline__ void acc_edge(uint2 ua, uint2 uv, float s,
                                         float4& acc) {
    __half2 p0 = __hadd2(*reinterpret_cast<__half2*>(&ua.x),
                         *reinterpret_cast<__half2*>(&uv.x));
    __half2 p1 = __hadd2(*reinterpret_cast<__half2*>(&ua.y),
                         *reinterpret_cast<__half2*>(&uv.y));
    float2 f0 = __half22float2(p0);
    float2 f1 = __half22float2(p1);
    acc.x += f0.x * s; acc.y += f0.y * s;
    acc.z += f1.x * s; acc.w += f1.y * s;
}

__global__ void aggregate_kernel(const float* __restrict__ ab,
                                 const float* __restrict__ ent,
                                 float* __restrict__ out) {
    int warp = (blockIdx.x * blockDim.x + threadIdx.x) >> 5;
    int lane = threadIdx.x & 31;
    if (warp >= N_NODES) return;
    int beg = g_off[warp];
    int deg = g_deg[warp];

    float sent_h = g_sent[warp] + __ldg(&ab[0]);   // uniform for the warp

    float4 acc = make_float4(0.f, 0.f, 0.f, 0.f);
    float rs_acc = 0.f;

    for (int base = 0; base < deg; base += 32) {
        int2 r = make_int2(0, 0);
        float s_lane = 0.f;
        if (base + lane < deg) {
            r = g_csr8[beg + base + lane];
            float s = sent_h + g_satt[r.x];
            s = s > 0.f ? s : 0.2f * s;            // leaky_relu(0.2)
            s_lane = __expf(s);
        }
        rs_acc += s_lane;
        int m = min(32, deg - base);
        for (int i = 0; i < m; i += 8) {
            uint2 UA[8], UV[8];
            float S[8];
            #pragma unroll
            for (int u = 0; u < 8; u++) {
                int j = i + u;
                int jj = (j < m) ? j : i;          // clamp: slot i always valid
                int a = __shfl_sync(0xFFFFFFFFu, r.x, jj);
                int v = __shfl_sync(0xFFFFFFFFu, r.y, jj);
                float s = __shfl_sync(0xFFFFFFFFu, s_lane, jj);
                S[u]  = (j < m) ? s : 0.f;
                UA[u] = *reinterpret_cast<const uint2*>(
                    g_attP + (size_t)a * KD + lane * 4);
                UV[u] = *reinterpret_cast<const uint2*>(
                    g_valP + (size_t)v * KD + lane * 4);
            }
            #pragma unroll
            for (int u = 0; u < 8; u++)
                acc_edge(UA[u], UV[u], S[u], acc);
        }
    }

    #pragma unroll
    for (int o = 16; o; o >>= 1)
        rs_acc += __shfl_xor_sync(0xFFFFFFFFu, rs_acc, o);
    float inv = rs_acc > 0.f ? 1.f / rs_acc : 0.f;

    float4 e = reinterpret_cast<const float4*>(ent)[warp * 32 + lane];
    float t0 = acc.x * inv + e.x;
    float t1 = acc.y * inv + e.y;
    float t2 = acc.z * inv + e.z;
    float t3 = acc.w * inv + e.w;
    float4 o;
    o.x = t0 > 0.f ? t0 : expm1f(t0);   // elu, alpha=1
    o.y = t1 > 0.f ? t1 : expm1f(t1);
    o.z = t2 > 0.f ? t2 : expm1f(t2);
    o.w = t3 > 0.f ? t3 : expm1f(t3);
    reinterpret_cast<float4*>(out)[warp * 32 + lane] = o;
}

// ---------------- launch ----------------------------------------------------
#define PROJ128_SMEM (64 * 136 * 2 + 128 * 136 * 2 + 64 * 132 * 4)   // 86016
#define PROJ64_SMEM  (64 * 72 * 2  + 128 * 72 * 2  + 64 * 132 * 4)   // 61440

extern "C" void kernel_launch(void* const* d_in, const int* in_sizes, int n_in,
                              void* d_out, int out_size) {
    const void*  triples = d_in[0];                       // [1e6, 3] int64/int32
    const float* ent     = (const float*)d_in[1];         // [1e5, 128]
    const float* attf    = (const float*)d_in[2];         // [1e5, 128]
    const float* valf    = (const float*)d_in[3];         // [1e5, 64]
    const float* aw      = (const float*)d_in[4];         // [256]
    const float* ab      = (const float*)d_in[5];         // [1]
    const float* W       = (const float*)d_in[6];         // [192, 128]
    float* out           = (float*)d_out;                 // [1e5, 128]

    static bool init_done = false;
    static cudaStream_t s1, s2;
    static cudaEvent_t ev_fork, ev_pp, ev_b1, ev_b2;
    if (!init_done) {
        cudaFuncSetAttribute(proj_kernel<128>,
                             cudaFuncAttributeMaxDynamicSharedMemorySize,
                             PROJ128_SMEM);
        cudaFuncSetAttribute(proj_kernel<64>,
                             cudaFuncAttributeMaxDynamicSharedMemorySize,
                             PROJ64_SMEM);
        cudaStreamCreateWithFlags(&s1, cudaStreamNonBlocking);
        cudaStreamCreateWithFlags(&s2, cudaStreamNonBlocking);
        cudaEventCreateWithFlags(&ev_fork, cudaEventDisableTiming);
        cudaEventCreateWithFlags(&ev_pp, cudaEventDisableTiming);
        cudaEventCreateWithFlags(&ev_b1, cudaEventDisableTiming);
        cudaEventCreateWithFlags(&ev_b2, cudaEventDisableTiming);
        init_done = true;
    }

    __half* attP; cudaGetSymbolAddress((void**)&attP, g_attP);
    __half* valP; cudaGetSymbolAddress((void**)&valP, g_valP);

    // launch 1: sniff + deg reset (branch A head)
    sniff_reset_kernel<<<NBLK, 256>>>((const int*)triples);

    cudaEventRecord(ev_fork, 0);
    cudaStreamWaitEvent(s1, ev_fork, 0);
    cudaStreamWaitEvent(s2, ev_fork, 0);

    // s1: prepack -> proj128 (launch 4 = proj128 -> profiled)
    prepack_kernel<<<(KD * WK + 255) / 256, 256, 0, s1>>>(W);    // launch 2
    cudaEventRecord(ev_pp, s1);
    score_pre_kernel<<<(N_NODES + 7) / 8, 256, 0, s2>>>(ent, attf, aw); // 3
    proj_kernel<128><<<296, 256, PROJ128_SMEM, s1>>>(attf, attP, 0);    // 4
    cudaEventRecord(ev_b1, s1);

    // s2: score_pre -> (wait prepack) proj64
    cudaStreamWaitEvent(s2, ev_pp, 0);
    proj_kernel<64><<<296, 256, PROJ64_SMEM, s2>>>(valf, valP, KD);     // 5
    cudaEventRecord(ev_b2, s2);

    // branch A (default): deg -> scans -> fill
    deg_kernel<<<(N_EDGES + 255) / 256, 256>>>((const int*)triples);
    scan_a_kernel<<<NBLK, 256>>>();
    scan_b_kernel<<<1, 512>>>();
    scan_c_kernel<<<NBLK, 256>>>();
    fill_kernel<<<(N_EDGES + 255) / 256, 256>>>(triples);

    // join: aggregate needs projections + scores (s1/s2) and CSR (default)
    cudaStreamWaitEvent(0, ev_b1, 0);
    cudaStreamWaitEvent(0, ev_b2, 0);
    aggregate_kernel<<<(N_NODES * 32 + 255) / 256, 256>>>(ab, ent, out);
}

// round 17
// speedup vs baseline: 1.2587x; 1.0162x over previous
#include <cuda_runtime.h>
#include <cuda_fp16.h>
#include <mma.h>
#include <math.h>
#include <cstdint>

using namespace nvcuda;

#define N_NODES 100000
#define N_EDGES 1000000
#define KD 128
#define VD 64
#define WK 192     // W rows (K of the original GEMM)
#define NBLK 391   // ceil(N_NODES / 256)

// ---------------- scratch (static device allocations, graph-safe) ----------
__device__ __align__(16) int2   g_csr8[N_EDGES];         // CSR-ordered {a, v}
__device__ __align__(16) __half g_attP[N_NODES * KD];    // att @ W[0:128]
__device__ __align__(16) __half g_valP[N_NODES * KD];    // val @ W[128:192]
__device__ __align__(16) __half g_Wt[KD * WK];           // Wt[n][k] = W[k][n]
__device__ float g_sent[N_NODES];
__device__ float g_satt[N_NODES];
__device__ int   g_deg[N_NODES];
__device__ int   g_off[N_NODES];
__device__ int   g_cursor[N_NODES];
__device__ int   g_bsum[NBLK];
__device__ int   g_boff[NBLK];
__device__ int   g_idx64;

// ------- dtype sniff (block 0) + deg reset (all blocks) ---------------------
__global__ void sniff_reset_kernel(const int* tri32) {
    int i = blockIdx.x * 256 + threadIdx.x;
    if (i < N_NODES) g_deg[i] = 0;
    if (blockIdx.x == 0) {
        int bad = (tri32[2 * threadIdx.x + 1] != 0) ? 1 : 0;
        int any = __syncthreads_or(bad);
        if (threadIdx.x == 0) g_idx64 = any ? 0 : 1;
    }
}

// ---------------- prepack W^T as fp16: Wt[n][k] = W[k][n] (once) ------------
__global__ void prepack_kernel(const float* __restrict__ W) {
    int idx = blockIdx.x * blockDim.x + threadIdx.x;   // n fast -> coalesced read
    if (idx >= KD * WK) return;
    int k = idx / KD;
    int n = idx % KD;
    g_Wt[n * WK + k] = __float2half_rn(W[idx]);
}

// ------- per-node score pre-reduction ----------------------------------------
__global__ void score_pre_kernel(const float* __restrict__ ent,
                                 const float* __restrict__ att,
                                 const float* __restrict__ aw) {
    int warp = (blockIdx.x * blockDim.x + threadIdx.x) >> 5;
    int lane = threadIdx.x & 31;
    if (warp >= N_NODES) return;

    const float4* ent4 = reinterpret_cast<const float4*>(ent);
    const float4* att4 = reinterpret_cast<const float4*>(att);
    const float4* aw4  = reinterpret_cast<const float4*>(aw);

    float4 e = ent4[warp * 32 + lane];
    float4 a = att4[warp * 32 + lane];
    float4 we = __ldg(&aw4[lane]);
    float4 wa = __ldg(&aw4[32 + lane]);

    float se = e.x * we.x + e.y * we.y + e.z * we.z + e.w * we.w;
    float sa = a.x * wa.x + a.y * wa.y + a.z * wa.z + a.w * wa.w;
    #pragma unroll
    for (int o = 16; o; o >>= 1) {
        se += __shfl_xor_sync(0xFFFFFFFFu, se, o);
        sa += __shfl_xor_sync(0xFFFFFFFFu, sa, o);
    }
    if (lane == 0) {
        g_sent[warp] = se;
        g_satt[warp] = sa;
    }
}

// ======== projection GEMM via wmma: dst = fp16(src[N,K] @ W[woff:woff+K]) ===
// 256 thr, 8 warps, tile 64 rows x 128 cols, persistent grid.
// As ALIASED into the Ds region (A dead before D store; guarded by sync) ->
// smem 68.6KB (K=128) / 52.2KB (K=64) -> 3-4 CTAs/SM (occ 37.5-50%).
#define PROJ_TILES 1563                     // ceil(100000 / 64)
#define DS_BYTES (64 * 132 * 4)             // 33792; As fits inside (<= 17408)

template <int K, int MAXB>
__global__ void __launch_bounds__(256, MAXB)
proj_kernel(const float* __restrict__ src, __half* __restrict__ dst, int woff) {
    constexpr int STRIDE = K + 8;           // halves
    extern __shared__ char smem[];
    __half* As = reinterpret_cast<__half*>(smem);           // aliases Ds
    float*  Ds = reinterpret_cast<float*>(smem);            // [64][132]
    __half* Ws = reinterpret_cast<__half*>(smem + DS_BYTES);

    int tid = threadIdx.x;
    int wid = tid >> 5;
    int rg  = wid >> 1;     // row group 0..3 (16 rows each)
    int ch  = wid & 1;      // col half 0..1 (64 cols each)

    // stage Ws[n][0..K) = g_Wt[n][woff..woff+K): coalesced uint4 (8 halves)
    for (int i = tid; i < 128 * (K / 8); i += 256) {
        int n   = i / (K / 8);
        int off = i % (K / 8);
        *reinterpret_cast<uint4*>(Ws + n * STRIDE + off * 8) =
            __ldg(reinterpret_cast<const uint4*>(g_Wt + n * WK + woff) + off);
    }

    for (int tile = blockIdx.x; tile < PROJ_TILES; tile += gridDim.x) {
        __syncthreads();   // Ws ready / prev-iter Ds consumed
        // stage A (fp32 -> fp16): 64 rows x K/4 float4
        for (int i = tid; i < 64 * (K / 4); i += 256) {
            int row = i / (K / 4);
            int f4  = i % (K / 4);
            int node = tile * 64 + row;
            float4 v = (node < N_NODES)
                ? __ldg(reinterpret_cast<const float4*>(src + (size_t)node * K) + f4)
                : make_float4(0.f, 0.f, 0.f, 0.f);
            __half2 h0 = __floats2half2_rn(v.x, v.y);
            __half2 h1 = __floats2half2_rn(v.z, v.w);
            uint2 p;
            p.x = *reinterpret_cast<unsigned*>(&h0);
            p.y = *reinterpret_cast<unsigned*>(&h1);
            *reinterpret_cast<uint2*>(As + row * STRIDE + f4 * 4) = p;
        }
        __syncthreads();

        wmma::fragment<wmma::accumulator, 16, 16, 16, float> acc[4];
        #pragma unroll
        for (int n = 0; n < 4; n++) wmma::fill_fragment(acc[n], 0.f);

        #pragma unroll
        for (int k0 = 0; k0 < K; k0 += 16) {
            wmma::fragment<wmma::matrix_a, 16, 16, 16, __half, wmma::row_major> a;
            wmma::load_matrix_sync(a, As + rg * 16 * STRIDE + k0, STRIDE);
            #pragma unroll
            for (int n = 0; n < 4; n++) {
                wmma::fragment<wmma::matrix_b, 16, 16, 16, __half, wmma::col_major> b;
                wmma::load_matrix_sync(b, Ws + (ch * 64 + n * 16) * STRIDE + k0,
                                       STRIDE);
                wmma::mma_sync(acc[n], a, b, acc[n]);
            }
        }
        __syncthreads();   // all As reads done before Ds overwrites the alias

        #pragma unroll
        for (int n = 0; n < 4; n++)
            wmma::store_matrix_sync(Ds + rg * 16 * 132 + ch * 64 + n * 16,
                                    acc[n], 132, wmma::mem_row_major);
        __syncthreads();

        // fp16 pack + coalesced store: 64 rows x 64 half2
        for (int idx = tid; idx < 64 * 64; idx += 256) {
            int row = idx >> 6;
            int c2  = idx & 63;
            int node = tile * 64 + row;
            if (node < N_NODES) {
                float lo = Ds[row * 132 + c2 * 2];
                float hi = Ds[row * 132 + c2 * 2 + 1];
                __half2 h = __floats2half2_rn(lo, hi);
                *reinterpret_cast<unsigned*>(dst + (size_t)node * KD + c2 * 2) =
                    *reinterpret_cast<unsigned*>(&h);
            }
        }
    }
}

// ---------------- degree histogram (h column only) ---------------------------
__global__ void deg_kernel(const int* __restrict__ tri32) {
    int e = blockIdx.x * blockDim.x + threadIdx.x;
    if (e >= N_EDGES) return;
    int h = g_idx64 ? tri32[6 * e] : tri32[3 * e];
    atomicAdd(&g_deg[h], 1);
}

// ---------------- 3-phase exclusive scan over degrees -----------------------
__global__ void scan_a_kernel() {
    __shared__ int sh[256];
    int t = threadIdx.x, b = blockIdx.x;
    int node = b * 256 + t;
    sh[t] = (node < N_NODES) ? g_deg[node] : 0;
    __syncthreads();
    #pragma unroll
    for (int d = 128; d; d >>= 1) {
        if (t < d) sh[t] += sh[t + d];
        __syncthreads();
    }
    if (t == 0) g_bsum[b] = sh[0];
}

__global__ void scan_b_kernel() {
    __shared__ int sh[512];
    int t = threadIdx.x;
    int v = (t < NBLK) ? g_bsum[t] : 0;
    sh[t] = v;
    __syncthreads();
    #pragma unroll
    for (int d = 1; d < 512; d <<= 1) {
        int x = (t >= d) ? sh[t - d] : 0;
        __syncthreads();
        sh[t] += x;
        __syncthreads();
    }
    if (t < NBLK) g_boff[t] = sh[t] - v;   // exclusive
}

__global__ void scan_c_kernel() {
    __shared__ int sh[256];
    int t = threadIdx.x, b = blockIdx.x;
    int node = b * 256 + t;
    int v = (node < N_NODES) ? g_deg[node] : 0;
    sh[t] = v;
    __syncthreads();
    #pragma unroll
    for (int d = 1; d < 256; d <<= 1) {
        int x = (t >= d) ? sh[t - d] : 0;
        __syncthreads();
        sh[t] += x;
        __syncthreads();
    }
    if (node < N_NODES) {
        int off = g_boff[b] + sh[t] - v;
        g_off[node] = off;
        g_cursor[node] = off;
    }
}

// ---------------- CSR permute: {a, v} only ----------------------------------
__global__ void fill_kernel(const void* __restrict__ tri) {
    int e = blockIdx.x * blockDim.x + threadIdx.x;
    if (e >= N_EDGES) return;
    int h, a, v;
    if (g_idx64) {
        const long long* t = reinterpret_cast<const long long*>(tri) + 3LL * e;
        h = (int)t[0]; a = (int)t[1]; v = (int)t[2];
    } else {
        const int* t = reinterpret_cast<const int*>(tri) + 3 * e;
        h = t[0]; a = t[1]; v = t[2];
    }
    int pos = atomicAdd(&g_cursor[h], 1);
    g_csr8[pos] = make_int2(a, v);
}

// ------- FINAL aggregate: inline scoring + projected gathers + epilogue -----
__device__ __forceinline__ void acc_edge(uint2 ua, uint2 uv, float s,
                                         float4& acc) {
    __half2 p0 = __hadd2(*reinterpret_cast<__half2*>(&ua.x),
                         *reinterpret_cast<__half2*>(&uv.x));
    __half2 p1 = __hadd2(*reinterpret_cast<__half2*>(&ua.y),
                         *reinterpret_cast<__half2*>(&uv.y));
    float2 f0 = __half22float2(p0);
    float2 f1 = __half22float2(p1);
    acc.x += f0.x * s; acc.y += f0.y * s;
    acc.z += f1.x * s; acc.w += f1.y * s;
}

__global__ void aggregate_kernel(const float* __restrict__ ab,
                                 const float* __restrict__ ent,
                                 float* __restrict__ out) {
    int warp = (blockIdx.x * blockDim.x + threadIdx.x) >> 5;
    int lane = threadIdx.x & 31;
    if (warp >= N_NODES) return;
    int beg = g_off[warp];
    int deg = g_deg[warp];

    float sent_h = g_sent[warp] + __ldg(&ab[0]);   // uniform for the warp

    float4 acc = make_float4(0.f, 0.f, 0.f, 0.f);
    float rs_acc = 0.f;

    for (int base = 0; base < deg; base += 32) {
        int2 r = make_int2(0, 0);
        float s_lane = 0.f;
        if (base + lane < deg) {
            r = g_csr8[beg + base + lane];
            float s = sent_h + g_satt[r.x];
            s = s > 0.f ? s : 0.2f * s;            // leaky_relu(0.2)
            s_lane = __expf(s);
        }
        rs_acc += s_lane;
        int m = min(32, deg - base);
        for (int i = 0; i < m; i += 8) {
            uint2 UA[8], UV[8];
            float S[8];
            #pragma unroll
            for (int u = 0; u < 8; u++) {
                int j = i + u;
                int jj = (j < m) ? j : i;          // clamp: slot i always valid
                int a = __shfl_sync(0xFFFFFFFFu, r.x, jj);
                int v = __shfl_sync(0xFFFFFFFFu, r.y, jj);
                float s = __shfl_sync(0xFFFFFFFFu, s_lane, jj);
                S[u]  = (j < m) ? s : 0.f;
                UA[u] = *reinterpret_cast<const uint2*>(
                    g_attP + (size_t)a * KD + lane * 4);
                UV[u] = *reinterpret_cast<const uint2*>(
                    g_valP + (size_t)v * KD + lane * 4);
            }
            #pragma unroll
            for (int u = 0; u < 8; u++)
                acc_edge(UA[u], UV[u], S[u], acc);
        }
    }

    #pragma unroll
    for (int o = 16; o; o >>= 1)
        rs_acc += __shfl_xor_sync(0xFFFFFFFFu, rs_acc, o);
    float inv = rs_acc > 0.f ? 1.f / rs_acc : 0.f;

    float4 e = reinterpret_cast<const float4*>(ent)[warp * 32 + lane];
    float t0 = acc.x * inv + e.x;
    float t1 = acc.y * inv + e.y;
    float t2 = acc.z * inv + e.z;
    float t3 = acc.w * inv + e.w;
    float4 o;
    o.x = t0 > 0.f ? t0 : expm1f(t0);   // elu, alpha=1
    o.y = t1 > 0.f ? t1 : expm1f(t1);
    o.z = t2 > 0.f ? t2 : expm1f(t2);
    o.w = t3 > 0.f ? t3 : expm1f(t3);
    reinterpret_cast<float4*>(out)[warp * 32 + lane] = o;
}

// ---------------- launch ----------------------------------------------------
#define PROJ128_SMEM (DS_BYTES + 128 * 136 * 2)   // 33792 + 34816 = 68608
#define PROJ64_SMEM  (DS_BYTES + 128 * 72 * 2)    // 33792 + 18432 = 52224

extern "C" void kernel_launch(void* const* d_in, const int* in_sizes, int n_in,
                              void* d_out, int out_size) {
    const void*  triples = d_in[0];                       // [1e6, 3] int64/int32
    const float* ent     = (const float*)d_in[1];         // [1e5, 128]
    const float* attf    = (const float*)d_in[2];         // [1e5, 128]
    const float* valf    = (const float*)d_in[3];         // [1e5, 64]
    const float* aw      = (const float*)d_in[4];         // [256]
    const float* ab      = (const float*)d_in[5];         // [1]
    const float* W       = (const float*)d_in[6];         // [192, 128]
    float* out           = (float*)d_out;                 // [1e5, 128]

    static bool init_done = false;
    static cudaStream_t s1, s2;
    static cudaEvent_t ev_fork, ev_pp, ev_b1, ev_b2;
    if (!init_done) {
        cudaFuncSetAttribute((const void*)proj_kernel<128, 3>,
                             cudaFuncAttributeMaxDynamicSharedMemorySize,
                             PROJ128_SMEM);
        cudaFuncSetAttribute((const void*)proj_kernel<64, 4>,
                             cudaFuncAttributeMaxDynamicSharedMemorySize,
                             PROJ64_SMEM);
        cudaStreamCreateWithFlags(&s1, cudaStreamNonBlocking);
        cudaStreamCreateWithFlags(&s2, cudaStreamNonBlocking);
        cudaEventCreateWithFlags(&ev_fork, cudaEventDisableTiming);
        cudaEventCreateWithFlags(&ev_pp, cudaEventDisableTiming);
        cudaEventCreateWithFlags(&ev_b1, cudaEventDisableTiming);
        cudaEventCreateWithFlags(&ev_b2, cudaEventDisableTiming);
        init_done = true;
    }

    __half* attP; cudaGetSymbolAddress((void**)&attP, g_attP);
    __half* valP; cudaGetSymbolAddress((void**)&valP, g_valP);

    // launch 1: sniff + deg reset (branch A head)
    sniff_reset_kernel<<<NBLK, 256>>>((const int*)triples);

    cudaEventRecord(ev_fork, 0);
    cudaStreamWaitEvent(s1, ev_fork, 0);
    cudaStreamWaitEvent(s2, ev_fork, 0);

    // s1: prepack -> proj128 (launch 4 = proj128 -> profiled)
    prepack_kernel<<<(KD * WK + 255) / 256, 256, 0, s1>>>(W);    // launch 2
    cudaEventRecord(ev_pp, s1);
    score_pre_kernel<<<(N_NODES + 7) / 8, 256, 0, s2>>>(ent, attf, aw); // 3
    proj_kernel<128, 3><<<444, 256, PROJ128_SMEM, s1>>>(attf, attP, 0); // 4
    cudaEventRecord(ev_b1, s1);

    // s2: score_pre -> (wait prepack) proj64
    cudaStreamWaitEvent(s2, ev_pp, 0);
    proj_kernel<64, 4><<<592, 256, PROJ64_SMEM, s2>>>(valf, valP, KD);  // 5
    cudaEventRecord(ev_b2, s2);

    // branch A (default): deg -> scans -> fill
    deg_kernel<<<(N_EDGES + 255) / 256, 256>>>((const int*)triples);
    scan_a_kernel<<<NBLK, 256>>>();
    scan_b_kernel<<<1, 512>>>();
    scan_c_kernel<<<NBLK, 256>>>();
    fill_kernel<<<(N_EDGES + 255) / 256, 256>>>(triples);

    // join: aggregate needs projections + scores (s1/s2) and CSR (default)
    cudaStreamWaitEvent(0, ev_b1, 0);
    cudaStreamWaitEvent(0, ev_b2, 0);
    aggregate_kernel<<<(N_NODES * 32 + 255) / 256, 256>>>(ab, ent, out);
}